// round 7
// baseline (speedup 1.0000x reference)
#include <cuda_runtime.h>
#include <cuda_bf16.h>
#include <math.h>
#include <stdint.h>

#define BB 2
#define LL 2048
#define DMODEL 512
#define DINNER 1024
#define NSTATE 16
#define MTOT (BB*LL)          // 4096 rows

// ------------- scratch (static device memory; 256B-aligned) ----------------
__device__ __align__(256) float g_xz[(size_t)MTOT*2*DINNER];      // in_proj out (x | z)
__device__ __align__(256) float g_du[2][(size_t)MTOT*DINNER*2];   // {dt, x} interleaved
__device__ __align__(256) float g_xdbl[2][(size_t)MTOT*64];       // x_proj out (dt 32 | B/C interleaved 32)
__device__ __align__(256) float g_y[2][(size_t)MTOT*DINNER];      // scan output

// bf16 split operands (hi/lo)
__device__ __align__(256) __nv_bfloat16 g_hh[(size_t)MTOT*DMODEL];
__device__ __align__(256) __nv_bfloat16 g_hl[(size_t)MTOT*DMODEL];
__device__ __align__(256) __nv_bfloat16 g_wih[2048*512];
__device__ __align__(256) __nv_bfloat16 g_wil[2048*512];
__device__ __align__(256) __nv_bfloat16 g_xch[2][(size_t)MTOT*DINNER];
__device__ __align__(256) __nv_bfloat16 g_xcl[2][(size_t)MTOT*DINNER];
__device__ __align__(256) __nv_bfloat16 g_xwh[2][64*1024];
__device__ __align__(256) __nv_bfloat16 g_xwl[2][64*1024];
__device__ __align__(256) __nv_bfloat16 g_ach[(size_t)MTOT*DINNER];
__device__ __align__(256) __nv_bfloat16 g_acl[(size_t)MTOT*DINNER];
__device__ __align__(256) __nv_bfloat16 g_woh[512*1024];
__device__ __align__(256) __nv_bfloat16 g_wol[512*1024];

__device__ void* g_ptrs[24];

// ---------------- fused: g_ptrs init + all 4 weight splits --------------------
// x_proj weights get a ROW PERMUTATION so B/C come out interleaved in g_xdbl:
//   r < 32 -> r ; 32<=r<48 (B_j) -> 32+2j ; 48<=r<64 (C_j) -> 33+2j
__global__ void __launch_bounds__(256) wsplit_kernel(
    const float* __restrict__ w_in, const float* __restrict__ w_xf,
    const float* __restrict__ w_xb, const float* __restrict__ w_out)
{
    int bid = blockIdx.x, tid = threadIdx.x;
    if (bid == 0 && tid == 0) {
        g_ptrs[0]  = g_xch[0]; g_ptrs[1]  = g_xch[1];
        g_ptrs[2]  = g_xcl[0]; g_ptrs[3]  = g_xcl[1];
        g_ptrs[4]  = g_xwh[0]; g_ptrs[5]  = g_xwh[1];
        g_ptrs[6]  = g_xwl[0]; g_ptrs[7]  = g_xwl[1];
        g_ptrs[8]  = g_xdbl[0]; g_ptrs[9] = g_xdbl[1];
        g_ptrs[10] = g_hh;  g_ptrs[11] = g_hl;
        g_ptrs[12] = g_wih; g_ptrs[13] = g_wil;
        g_ptrs[14] = g_xz;
        g_ptrs[15] = g_ach; g_ptrs[16] = g_acl;
        g_ptrs[17] = g_woh; g_ptrs[18] = g_wol;
        g_ptrs[20] = g_du[0]; g_ptrs[21] = g_du[1];
    }
    if (bid < 4096) {                       // in_proj_w: 1M elems
        int i = bid * 256 + tid;
        float x = w_in[i];
        __nv_bfloat16 h = __float2bfloat16(x);
        g_wih[i] = h;
        g_wil[i] = __float2bfloat16(x - __bfloat162float(h));
    } else if (bid < 4608) {                // x_proj_w fwd/bwd: 2 x 64K, permuted rows
        int z = (bid - 4096) >> 8;          // 0: fwd, 1: bwd
        int i = ((bid - 4096) & 255) * 256 + tid;
        int r = i >> 10, c = i & 1023;
        int rr = (r < 32) ? r : ((r < 48) ? (2*r - 32) : (2*r - 63));
        const float* src = z ? w_xb : w_xf;
        float x = src[i];
        __nv_bfloat16 h = __float2bfloat16(x);
        int o = rr * 1024 + c;
        g_xwh[z][o] = h;
        g_xwl[z][o] = __float2bfloat16(x - __bfloat162float(h));
    } else {                                // out_proj_w: 512K
        int i = (bid - 4608) * 256 + tid;
        float x = w_out[i];
        __nv_bfloat16 h = __float2bfloat16(x);
        g_woh[i] = h;
        g_wol[i] = __float2bfloat16(x - __bfloat162float(h));
    }
}

// ====================== baseline-PTX helpers (sm_80-level) ======================
__device__ __forceinline__ uint32_t smem_u32(const void* p) {
    uint32_t a;
    asm("{ .reg .u64 t; cvta.to.shared.u64 t, %1; cvt.u32.u64 %0, t; }" : "=r"(a) : "l"(p));
    return a;
}
#define LDSM4(r, addr) \
    asm volatile("ldmatrix.sync.aligned.m8n8.x4.shared.b16 {%0,%1,%2,%3}, [%4];" \
        : "=r"((r)[0]), "=r"((r)[1]), "=r"((r)[2]), "=r"((r)[3]) : "r"(addr))
#define MMA16816(d, a, b0, b1) \
    asm volatile("mma.sync.aligned.m16n8k16.row.col.f32.bf16.bf16.f32 " \
        "{%0,%1,%2,%3},{%4,%5,%6,%7},{%8,%9},{%0,%1,%2,%3};" \
        : "+f"((d)[0]), "+f"((d)[1]), "+f"((d)[2]), "+f"((d)[3]) \
        : "r"((a)[0]), "r"((a)[1]), "r"((a)[2]), "r"((a)[3]), "r"(b0), "r"(b1))
#define CP_ASYNC16(saddr, gaddr) \
    asm volatile("cp.async.cg.shared.global [%0], [%1], 16;" :: "r"(saddr), "l"(gaddr))
#define CP_COMMIT() asm volatile("cp.async.commit_group;")
#define CP_WAIT(n)  asm volatile("cp.async.wait_group %0;" :: "n"(n))

// ====================== split-bf16 warp-MMA GEMM =============================
// C[M,N] = (Ah+Al)[M,K] @ (Bh+Bl)[N,K]^T via 3 passes (AhBh + AlBh + AhBl).
// BM=128, BN in {128,64}, BK=32, 256 threads. SMEM rows padded to 40 bf16.
template<int BN>
__global__ void __launch_bounds__(256) mma_gemm(
    int ahi, int alo, int bhi, int blo, int c_id,
    float* Cext, int K, int ldc)
{
    extern __shared__ char smem[];
    const int z = blockIdx.z;
    const __nv_bfloat16* Ah = (const __nv_bfloat16*)g_ptrs[ahi + z];
    const __nv_bfloat16* Al = (const __nv_bfloat16*)g_ptrs[alo + z];
    const __nv_bfloat16* Bh = (const __nv_bfloat16*)g_ptrs[bhi + z];
    const __nv_bfloat16* Bl = (const __nv_bfloat16*)g_ptrs[blo + z];
    float* C = (c_id >= 0) ? (float*)g_ptrs[c_id + z] : Cext;

    constexpr int WN  = BN / 2;
    constexpr int NT8 = WN / 8;
    constexpr int NG  = NT8 / 2;
    constexpr int ASZ = 128 * 40 * 2;
    constexpr int BSZ = BN * 40 * 2;
    constexpr int STG = ASZ + BSZ;

    const int tid  = threadIdx.x;
    const int lane = tid & 31, wid = tid >> 5;
    const int wm = wid >> 1, wn = wid & 1;
    const int bm = blockIdx.y * 128, bn = blockIdx.x * BN;
    uint32_t sb = smem_u32(smem);

    const int KC = K / 32;
    const int NI = 3 * KC;

    const int lrow = (lane & 7) + (wid << 3);
    const int lchk = (lane >> 3) & 3;

    auto load_stage = [&](int i, int s) {
        int pass = i / KC;
        int k0 = (i - pass * KC) * 32;
        const __nv_bfloat16* sA = (pass == 1) ? Al : Ah;
        const __nv_bfloat16* sB = (pass == 2) ? Bl : Bh;
        uint32_t as = sb + s * STG;
        uint32_t bs = as + ASZ;
#pragma unroll
        for (int h = 0; h < 2; h++) {
            int r = lrow + h * 64;
            CP_ASYNC16(as + (r * 40 + lchk * 8) * 2,
                       sA + (size_t)(bm + r) * K + k0 + lchk * 8);
        }
#pragma unroll
        for (int h = 0; h < BN / 64; h++) {
            int r = lrow + h * 64;
            CP_ASYNC16(bs + (r * 40 + lchk * 8) * 2,
                       sB + (size_t)(bn + r) * K + k0 + lchk * 8);
        }
        CP_COMMIT();
    };

    float acc[2][NT8][4];
#pragma unroll
    for (int mt = 0; mt < 2; mt++)
#pragma unroll
        for (int nt = 0; nt < NT8; nt++)
#pragma unroll
            for (int q = 0; q < 4; q++) acc[mt][nt][q] = 0.f;

    load_stage(0, 0);
    for (int i = 0; i < NI; i++) {
        int s = i & 1;
        if (i + 1 < NI) { load_stage(i + 1, s ^ 1); CP_WAIT(1); }
        else             { CP_WAIT(0); }
        __syncthreads();
        uint32_t as = sb + s * STG, bs = as + ASZ;
#pragma unroll
        for (int kk = 0; kk < 2; kk++) {
            uint32_t a[2][4];
            int kc = kk * 2 + (lane >> 4);
#pragma unroll
            for (int mt = 0; mt < 2; mt++) {
                int r = wm * 32 + mt * 16 + (lane & 15);
                LDSM4(a[mt], as + (r * 40 + kc * 8) * 2);
            }
            uint32_t b[NG][4];
            int bc = kk * 2 + ((lane >> 3) & 1);
            int brl = (lane & 7) + ((lane >> 4) << 3);
#pragma unroll
            for (int g = 0; g < NG; g++) {
                int r = wn * WN + g * 16 + brl;
                LDSM4(b[g], bs + (r * 40 + bc * 8) * 2);
            }
#pragma unroll
            for (int mt = 0; mt < 2; mt++)
#pragma unroll
                for (int nt = 0; nt < NT8; nt++)
                    MMA16816(acc[mt][nt], a[mt],
                             b[nt >> 1][(nt & 1) * 2], b[nt >> 1][(nt & 1) * 2 + 1]);
        }
        __syncthreads();
    }

#pragma unroll
    for (int mt = 0; mt < 2; mt++) {
        int r0 = bm + wm * 32 + mt * 16 + (lane >> 2);
#pragma unroll
        for (int nt = 0; nt < NT8; nt++) {
            int cc = bn + wn * WN + nt * 8 + (lane & 3) * 2;
            *(float2*)&C[(size_t)r0 * ldc + cc] =
                make_float2(acc[mt][nt][0], acc[mt][nt][1]);
            *(float2*)&C[(size_t)(r0 + 8) * ldc + cc] =
                make_float2(acc[mt][nt][2], acc[mt][nt][3]);
        }
    }
}

// ---------------- layernorm + residual + bf16 split ----------------
__global__ void __launch_bounds__(128) ln_kernel(
    const float* __restrict__ x, const float* __restrict__ w,
    const float* __restrict__ bb, float* __restrict__ resid)
{
    int row = blockIdx.x;
    const float* xr = x + (size_t)row * DMODEL;
    int tid = threadIdx.x;
    float v[4];
    float s = 0.f;
#pragma unroll
    for (int i = 0; i < 4; i++) { v[i] = xr[tid + i*128]; s += v[i]; }
#pragma unroll
    for (int o = 16; o; o >>= 1) s += __shfl_xor_sync(0xffffffffu, s, o);
    __shared__ float red[8];
    if ((tid & 31) == 0) red[tid >> 5] = s;
    __syncthreads();
    float mu = (red[0] + red[1] + red[2] + red[3]) * (1.f / DMODEL);
    float q = 0.f;
#pragma unroll
    for (int i = 0; i < 4; i++) { float c = v[i] - mu; q += c * c; }
#pragma unroll
    for (int o = 16; o; o >>= 1) q += __shfl_xor_sync(0xffffffffu, q, o);
    if ((tid & 31) == 0) red[4 + (tid >> 5)] = q;
    __syncthreads();
    float var = (red[4] + red[5] + red[6] + red[7]) * (1.f / DMODEL);
    float rs = rsqrtf(var + 1e-5f);
#pragma unroll
    for (int i = 0; i < 4; i++) {
        int c = tid + i*128;
        float hv = (v[i] - mu) * rs * w[c] + bb[c];
        size_t idx = (size_t)row * DMODEL + c;
        __nv_bfloat16 hh = __float2bfloat16(hv);
        g_hh[idx] = hh;
        g_hl[idx] = __float2bfloat16(hv - __bfloat162float(hh));
        resid[idx] = v[i];
    }
}

// ---------------- fp32 SGEMM (dt_proj): C = A[M,K] @ B[N,K]^T ---------------
// EPI==1: softplus(C + bias[n]) stored INTERLEAVED into g_du slot 0.
template<int EPI>
__global__ void __launch_bounds__(256) sgemm_nt(
    int a_id, int lda, const float* __restrict__ Bw, int ldb,
    float* __restrict__ Cext, int c_id, int ldc,
    int Kd, const float* __restrict__ bias)
{
    const float* __restrict__ A = (const float*)g_ptrs[a_id];
    float* __restrict__ C = (c_id >= 0) ? (float*)g_ptrs[c_id] : Cext;
    __shared__ float As[16][132];
    __shared__ float Bs[16][68];
    int tid = threadIdx.x;
    int bm = blockIdx.y * 128, bn = blockIdx.x * 64;
    int tx = tid & 15, ty = tid >> 4;
    int arow = tid >> 1, ak = (tid & 1) * 8;
    int brow = tid >> 2, bk = (tid & 3) * 4;
    const float* Ag = A + (size_t)(bm + arow) * lda + ak;
    const float* Bg = Bw + (size_t)(bn + brow) * ldb + bk;
    float acc[8][4];
#pragma unroll
    for (int i = 0; i < 8; i++)
#pragma unroll
        for (int j = 0; j < 4; j++) acc[i][j] = 0.f;

    for (int k0 = 0; k0 < Kd; k0 += 16) {
        float4 a0 = *(const float4*)(Ag + k0);
        float4 a1 = *(const float4*)(Ag + k0 + 4);
        float4 b0 = *(const float4*)(Bg + k0);
        __syncthreads();
        As[ak+0][arow] = a0.x; As[ak+1][arow] = a0.y;
        As[ak+2][arow] = a0.z; As[ak+3][arow] = a0.w;
        As[ak+4][arow] = a1.x; As[ak+5][arow] = a1.y;
        As[ak+6][arow] = a1.z; As[ak+7][arow] = a1.w;
        Bs[bk+0][brow] = b0.x; Bs[bk+1][brow] = b0.y;
        Bs[bk+2][brow] = b0.z; Bs[bk+3][brow] = b0.w;
        __syncthreads();
#pragma unroll
        for (int k = 0; k < 16; k++) {
            float4 m0 = *(const float4*)&As[k][ty*8];
            float4 m1 = *(const float4*)&As[k][ty*8 + 4];
            float4 n0 = *(const float4*)&Bs[k][tx*4];
            float am[8] = {m0.x, m0.y, m0.z, m0.w, m1.x, m1.y, m1.z, m1.w};
            float bv[4] = {n0.x, n0.y, n0.z, n0.w};
#pragma unroll
            for (int i = 0; i < 8; i++)
#pragma unroll
                for (int j = 0; j < 4; j++)
                    acc[i][j] = fmaf(am[i], bv[j], acc[i][j]);
        }
    }
#pragma unroll
    for (int i = 0; i < 8; i++) {
        if (EPI == 1) {
#pragma unroll
            for (int j = 0; j < 4; j++) {
                float v = acc[i][j] + bias[bn + tx*4 + j];
                v = (v > 20.f) ? v : log1pf(expf(v));
                C[((size_t)(bm + ty*8 + i) * DINNER + bn + tx*4 + j) * 2] = v;
            }
        } else {
            float4 o; o.x = acc[i][0]; o.y = acc[i][1]; o.z = acc[i][2]; o.w = acc[i][3];
            *(float4*)&C[(size_t)(bm + ty*8 + i) * ldc + bn + tx*4] = o;
        }
    }
}

// ---------------- causal depthwise conv (K=4) + silu + splits -----------------
// Writes silu(conv) into g_du slot 1 (fp32) and bf16 hi/lo for x_proj GEMM.
__global__ void __launch_bounds__(256) conv_silu_kernel(
    const float* __restrict__ cw0, const float* __restrict__ cb0,
    const float* __restrict__ cw1, const float* __restrict__ cb1)
{
    int dir = blockIdx.y;
    unsigned e = blockIdx.x * 256 + threadIdx.x;
    int d = e & (DINNER - 1);
    int m = e >> 10;
    int b = m >> 11, t = m & (LL - 1);
    const float* cw = dir ? cw1 : cw0;
    const float* cb = dir ? cb1 : cb0;
    float acc = cb[d];
#pragma unroll
    for (int k = 0; k < 4; k++) {
        int s = t - 3 + k;
        if (s >= 0) {
            int l = dir ? (LL - 1 - s) : s;
            acc += cw[d*4 + k] * g_xz[(size_t)((b << 11) + l) * (2*DINNER) + d];
        }
    }
    float sv = acc / (1.f + __expf(-acc));
    g_du[dir][(size_t)e * 2 + 1] = sv;
    __nv_bfloat16 h = __float2bfloat16(sv);
    g_xch[dir][e] = h;
    g_xcl[dir][e] = __float2bfloat16(sv - __bfloat162float(h));
}

// ---------------- selective scan: 16 lanes = 16 states, 2 channels/warp -------
// {dt,x} as one float2 load; {B,C} as one float2 load (pre-interleaved).
__global__ void __launch_bounds__(256) scan_kernel(
    const float* __restrict__ A_log0, const float* __restrict__ Dp0,
    const float* __restrict__ A_log1, const float* __restrict__ Dp1)
{
    int dir = blockIdx.y;
    const float* A_log = dir ? A_log1 : A_log0;
    const float* Dp    = dir ? Dp1    : Dp0;
    int tid = threadIdx.x;
    int w = tid >> 5, lane = tid & 31, half = lane >> 4, n = lane & 15;
    int c = blockIdx.x * 16 + w*2 + half;
    int b = c >> 10, d = c & (DINNER - 1);
    float Acoef = -expf(A_log[d*NSTATE + n]);
    float Dd = Dp[d];
    const float2* pdu = (const float2*)&g_du[dir][((size_t)(b*LL) * DINNER + d) * 2];
    const float2* pbc = (const float2*)&g_xdbl[dir][(size_t)(b*LL) * 64 + 32 + 2*n];
    float* py = &g_y[dir][(size_t)(b*LL) * DINNER + d];
    float h = 0.f;
#pragma unroll 4
    for (int t = 0; t < LL; t++) {
        float2 du = *pdu;          // {dt, x}
        float2 bc = *pbc;          // {B_n, C_n}
        float dA = __expf(du.x * Acoef);
        h = fmaf(dA, h, du.x * bc.x * du.y);
        float p = h * bc.y;
        p += __shfl_xor_sync(0xffffffffu, p, 8);
        p += __shfl_xor_sync(0xffffffffu, p, 4);
        p += __shfl_xor_sync(0xffffffffu, p, 2);
        p += __shfl_xor_sync(0xffffffffu, p, 1);
        if (n == 0) *py = p + du.y * Dd;
        pdu += DINNER; pbc += 32; py += DINNER;
    }
}

// ---------------- combine: 0.5 * silu(z) * (y_f + rev(y_r)) -> bf16 split -----
__global__ void __launch_bounds__(256) combine_kernel()
{
    unsigned e = blockIdx.x * 256 + threadIdx.x;
    int d = e & (DINNER - 1);
    int m = e >> 10;
    int b = m >> 11, l = m & (LL - 1);
    float z = g_xz[(size_t)m * (2*DINNER) + DINNER + d];
    float sz = z / (1.f + __expf(-z));
    float yf = g_y[0][e];
    float yr = g_y[1][(size_t)((b << 11) + (LL - 1 - l)) * DINNER + d];
    float v = 0.5f * sz * (yf + yr);
    __nv_bfloat16 h = __float2bfloat16(v);
    g_ach[e] = h;
    g_acl[e] = __float2bfloat16(v - __bfloat162float(h));
}

// ---------------- launch ----------------
extern "C" void kernel_launch(void* const* d_in, const int* in_sizes, int n_in,
                              void* d_out, int out_size)
{
    const float* hs        = (const float*)d_in[0];
    const float* norm_w    = (const float*)d_in[1];
    const float* norm_b    = (const float*)d_in[2];
    const float* in_proj_w = (const float*)d_in[3];
    const float* out_proj_w= (const float*)d_in[4];
    const float* conv_w    = (const float*)d_in[5];
    const float* conv_b    = (const float*)d_in[6];
    const float* x_proj_w  = (const float*)d_in[7];
    const float* dt_proj_w = (const float*)d_in[8];
    const float* dt_proj_b = (const float*)d_in[9];
    const float* A_log     = (const float*)d_in[10];
    const float* Dp        = (const float*)d_in[11];
    const float* conv_w_b  = (const float*)d_in[12];
    const float* conv_b_b  = (const float*)d_in[13];
    const float* x_proj_w_b= (const float*)d_in[14];
    const float* dt_proj_w_b=(const float*)d_in[15];
    const float* dt_proj_b_b=(const float*)d_in[16];
    const float* A_log_b   = (const float*)d_in[17];
    const float* D_b       = (const float*)d_in[18];

    float* out   = (float*)d_out;
    float* resid = out + (size_t)MTOT * DMODEL;

    const int SM128 = 2 * (128*40*2 + 128*40*2);   // 40960 B
    const int SM64  = 2 * (128*40*2 + 64*40*2);    // 30720 B

    // fused g_ptrs init + weight splits (x_proj rows permuted for B/C interleave)
    wsplit_kernel<<<4096 + 512 + 2048, 256>>>(in_proj_w, x_proj_w, x_proj_w_b, out_proj_w);

    // layernorm + residual + h split
    ln_kernel<<<MTOT, 128>>>(hs, norm_w, norm_b, resid);

    // in_proj: g_xz[4096,2048] = h[4096,512] @ in_proj_w[2048,512]^T
    mma_gemm<128><<<dim3(2048/128, MTOT/128, 1), 256, SM128>>>(
        10, 11, 12, 13, 14, nullptr, DMODEL, 2048);

    // conv + silu -> g_du slot1 + bf16 split, both directions (scan order)
    conv_silu_kernel<<<dim3(MTOT*DINNER/256, 2), 256>>>(
        conv_w, conv_b, conv_w_b, conv_b_b);

    // x_proj both dirs: g_xdbl[4096,64] = xc @ x_proj_w_perm[64,1024]^T
    mma_gemm<64><<<dim3(1, MTOT/128, 2), 256, SM64>>>(
        0, 2, 4, 6, 8, nullptr, DINNER, 64);

    // dt per dir: softplus(xdbl[:, :32] @ dt_proj_w[1024,32]^T + bias) -> g_du slot0
    sgemm_nt<1><<<dim3(1024/64, MTOT/128), 256>>>(
        8, 64, dt_proj_w,   32, nullptr, 20, DINNER, 32, dt_proj_b);
    sgemm_nt<1><<<dim3(1024/64, MTOT/128), 256>>>(
        9, 64, dt_proj_w_b, 32, nullptr, 21, DINNER, 32, dt_proj_b_b);

    // selective scan, both directions
    scan_kernel<<<dim3(BB*DINNER/16, 2), 256>>>(A_log, Dp, A_log_b, D_b);

    // combine + silu(z) gating + split
    combine_kernel<<<(unsigned)((size_t)MTOT*DINNER/256), 256>>>();

    // out_proj: out[4096,512] = ac[4096,1024] @ out_proj_w[512,1024]^T
    mma_gemm<128><<<dim3(512/128, MTOT/128, 1), 256, SM128>>>(
        15, 16, 17, 18, -1, out, DINNER, DMODEL);
}

// round 8
// speedup vs baseline: 1.1896x; 1.1896x over previous
#include <cuda_runtime.h>
#include <cuda_bf16.h>
#include <math.h>
#include <stdint.h>

#define BB 2
#define LL 2048
#define DMODEL 512
#define DINNER 1024
#define NSTATE 16
#define MTOT (BB*LL)          // 4096 rows

// ------------- scratch (static device memory; 256B-aligned) ----------------
__device__ __align__(256) float g_xz[(size_t)MTOT*2*DINNER];      // in_proj out (x | z)
__device__ __align__(256) float g_xc[2][(size_t)MTOT*DINNER];     // conv+silu (scan order)
__device__ __align__(256) float g_dt[2][(size_t)MTOT*DINNER];     // softplus(dt)
__device__ __align__(256) float g_xdbl[2][(size_t)MTOT*64];       // x_proj out (dt 32 | B/C interleaved 32)
__device__ __align__(256) float g_y[2][(size_t)MTOT*DINNER];      // scan output

// bf16 split operands (hi/lo)
__device__ __align__(256) __nv_bfloat16 g_hh[(size_t)MTOT*DMODEL];
__device__ __align__(256) __nv_bfloat16 g_hl[(size_t)MTOT*DMODEL];
__device__ __align__(256) __nv_bfloat16 g_wih[2048*512];
__device__ __align__(256) __nv_bfloat16 g_wil[2048*512];
__device__ __align__(256) __nv_bfloat16 g_xch[2][(size_t)MTOT*DINNER];
__device__ __align__(256) __nv_bfloat16 g_xcl[2][(size_t)MTOT*DINNER];
__device__ __align__(256) __nv_bfloat16 g_xwh[2][64*1024];
__device__ __align__(256) __nv_bfloat16 g_xwl[2][64*1024];
__device__ __align__(256) __nv_bfloat16 g_ach[(size_t)MTOT*DINNER];
__device__ __align__(256) __nv_bfloat16 g_acl[(size_t)MTOT*DINNER];
__device__ __align__(256) __nv_bfloat16 g_woh[512*1024];
__device__ __align__(256) __nv_bfloat16 g_wol[512*1024];

__device__ void* g_ptrs[24];

// ---------------- fused: g_ptrs init + all 4 weight splits --------------------
// x_proj weights get a ROW PERMUTATION so B/C come out interleaved in g_xdbl:
//   r < 32 -> r ; 32<=r<48 (B_j) -> 32+2j ; 48<=r<64 (C_j) -> 33+2j
// (pure index remap at split time; GEMM + epilogue stay fully coalesced)
__global__ void __launch_bounds__(256) wsplit_kernel(
    const float* __restrict__ w_in, const float* __restrict__ w_xf,
    const float* __restrict__ w_xb, const float* __restrict__ w_out)
{
    int bid = blockIdx.x, tid = threadIdx.x;
    if (bid == 0 && tid == 0) {
        g_ptrs[0]  = g_xch[0]; g_ptrs[1]  = g_xch[1];
        g_ptrs[2]  = g_xcl[0]; g_ptrs[3]  = g_xcl[1];
        g_ptrs[4]  = g_xwh[0]; g_ptrs[5]  = g_xwh[1];
        g_ptrs[6]  = g_xwl[0]; g_ptrs[7]  = g_xwl[1];
        g_ptrs[8]  = g_xdbl[0]; g_ptrs[9] = g_xdbl[1];
        g_ptrs[10] = g_hh;  g_ptrs[11] = g_hl;
        g_ptrs[12] = g_wih; g_ptrs[13] = g_wil;
        g_ptrs[14] = g_xz;
        g_ptrs[15] = g_ach; g_ptrs[16] = g_acl;
        g_ptrs[17] = g_woh; g_ptrs[18] = g_wol;
        g_ptrs[20] = g_dt[0]; g_ptrs[21] = g_dt[1];
    }
    if (bid < 4096) {                       // in_proj_w: 1M elems
        int i = bid * 256 + tid;
        float x = w_in[i];
        __nv_bfloat16 h = __float2bfloat16(x);
        g_wih[i] = h;
        g_wil[i] = __float2bfloat16(x - __bfloat162float(h));
    } else if (bid < 4608) {                // x_proj_w fwd/bwd: 2 x 64K, permuted rows
        int z = (bid - 4096) >> 8;          // 0: fwd, 1: bwd
        int i = ((bid - 4096) & 255) * 256 + tid;
        int r = i >> 10, c = i & 1023;
        int rr = (r < 32) ? r : ((r < 48) ? (2*r - 32) : (2*r - 63));
        const float* src = z ? w_xb : w_xf;
        float x = src[i];
        __nv_bfloat16 h = __float2bfloat16(x);
        int o = rr * 1024 + c;
        g_xwh[z][o] = h;
        g_xwl[z][o] = __float2bfloat16(x - __bfloat162float(h));
    } else {                                // out_proj_w: 512K
        int i = (bid - 4608) * 256 + tid;
        float x = w_out[i];
        __nv_bfloat16 h = __float2bfloat16(x);
        g_woh[i] = h;
        g_wol[i] = __float2bfloat16(x - __bfloat162float(h));
    }
}

// ====================== baseline-PTX helpers (sm_80-level) ======================
__device__ __forceinline__ uint32_t smem_u32(const void* p) {
    uint32_t a;
    asm("{ .reg .u64 t; cvta.to.shared.u64 t, %1; cvt.u32.u64 %0, t; }" : "=r"(a) : "l"(p));
    return a;
}
#define LDSM4(r, addr) \
    asm volatile("ldmatrix.sync.aligned.m8n8.x4.shared.b16 {%0,%1,%2,%3}, [%4];" \
        : "=r"((r)[0]), "=r"((r)[1]), "=r"((r)[2]), "=r"((r)[3]) : "r"(addr))
#define MMA16816(d, a, b0, b1) \
    asm volatile("mma.sync.aligned.m16n8k16.row.col.f32.bf16.bf16.f32 " \
        "{%0,%1,%2,%3},{%4,%5,%6,%7},{%8,%9},{%0,%1,%2,%3};" \
        : "+f"((d)[0]), "+f"((d)[1]), "+f"((d)[2]), "+f"((d)[3]) \
        : "r"((a)[0]), "r"((a)[1]), "r"((a)[2]), "r"((a)[3]), "r"(b0), "r"(b1))
#define CP_ASYNC16(saddr, gaddr) \
    asm volatile("cp.async.cg.shared.global [%0], [%1], 16;" :: "r"(saddr), "l"(gaddr))
#define CP_COMMIT() asm volatile("cp.async.commit_group;")
#define CP_WAIT(n)  asm volatile("cp.async.wait_group %0;" :: "n"(n))

// ====================== split-bf16 warp-MMA GEMM =============================
// C[M,N] = (Ah+Al)[M,K] @ (Bh+Bl)[N,K]^T via 3 passes (AhBh + AlBh + AhBl).
// BM=128, BN in {128,64}, BK=32, 256 threads. SMEM rows padded to 40 bf16.
template<int BN>
__global__ void __launch_bounds__(256) mma_gemm(
    int ahi, int alo, int bhi, int blo, int c_id,
    float* Cext, int K, int ldc)
{
    extern __shared__ char smem[];
    const int z = blockIdx.z;
    const __nv_bfloat16* Ah = (const __nv_bfloat16*)g_ptrs[ahi + z];
    const __nv_bfloat16* Al = (const __nv_bfloat16*)g_ptrs[alo + z];
    const __nv_bfloat16* Bh = (const __nv_bfloat16*)g_ptrs[bhi + z];
    const __nv_bfloat16* Bl = (const __nv_bfloat16*)g_ptrs[blo + z];
    float* C = (c_id >= 0) ? (float*)g_ptrs[c_id + z] : Cext;

    constexpr int WN  = BN / 2;
    constexpr int NT8 = WN / 8;
    constexpr int NG  = NT8 / 2;
    constexpr int ASZ = 128 * 40 * 2;
    constexpr int BSZ = BN * 40 * 2;
    constexpr int STG = ASZ + BSZ;

    const int tid  = threadIdx.x;
    const int lane = tid & 31, wid = tid >> 5;
    const int wm = wid >> 1, wn = wid & 1;
    const int bm = blockIdx.y * 128, bn = blockIdx.x * BN;
    uint32_t sb = smem_u32(smem);

    const int KC = K / 32;
    const int NI = 3 * KC;

    const int lrow = (lane & 7) + (wid << 3);
    const int lchk = (lane >> 3) & 3;

    auto load_stage = [&](int i, int s) {
        int pass = i / KC;
        int k0 = (i - pass * KC) * 32;
        const __nv_bfloat16* sA = (pass == 1) ? Al : Ah;
        const __nv_bfloat16* sB = (pass == 2) ? Bl : Bh;
        uint32_t as = sb + s * STG;
        uint32_t bs = as + ASZ;
#pragma unroll
        for (int h = 0; h < 2; h++) {
            int r = lrow + h * 64;
            CP_ASYNC16(as + (r * 40 + lchk * 8) * 2,
                       sA + (size_t)(bm + r) * K + k0 + lchk * 8);
        }
#pragma unroll
        for (int h = 0; h < BN / 64; h++) {
            int r = lrow + h * 64;
            CP_ASYNC16(bs + (r * 40 + lchk * 8) * 2,
                       sB + (size_t)(bn + r) * K + k0 + lchk * 8);
        }
        CP_COMMIT();
    };

    float acc[2][NT8][4];
#pragma unroll
    for (int mt = 0; mt < 2; mt++)
#pragma unroll
        for (int nt = 0; nt < NT8; nt++)
#pragma unroll
            for (int q = 0; q < 4; q++) acc[mt][nt][q] = 0.f;

    load_stage(0, 0);
    for (int i = 0; i < NI; i++) {
        int s = i & 1;
        if (i + 1 < NI) { load_stage(i + 1, s ^ 1); CP_WAIT(1); }
        else             { CP_WAIT(0); }
        __syncthreads();
        uint32_t as = sb + s * STG, bs = as + ASZ;
#pragma unroll
        for (int kk = 0; kk < 2; kk++) {
            uint32_t a[2][4];
            int kc = kk * 2 + (lane >> 4);
#pragma unroll
            for (int mt = 0; mt < 2; mt++) {
                int r = wm * 32 + mt * 16 + (lane & 15);
                LDSM4(a[mt], as + (r * 40 + kc * 8) * 2);
            }
            uint32_t b[NG][4];
            int bc = kk * 2 + ((lane >> 3) & 1);
            int brl = (lane & 7) + ((lane >> 4) << 3);
#pragma unroll
            for (int g = 0; g < NG; g++) {
                int r = wn * WN + g * 16 + brl;
                LDSM4(b[g], bs + (r * 40 + bc * 8) * 2);
            }
#pragma unroll
            for (int mt = 0; mt < 2; mt++)
#pragma unroll
                for (int nt = 0; nt < NT8; nt++)
                    MMA16816(acc[mt][nt], a[mt],
                             b[nt >> 1][(nt & 1) * 2], b[nt >> 1][(nt & 1) * 2 + 1]);
        }
        __syncthreads();
    }

#pragma unroll
    for (int mt = 0; mt < 2; mt++) {
        int r0 = bm + wm * 32 + mt * 16 + (lane >> 2);
#pragma unroll
        for (int nt = 0; nt < NT8; nt++) {
            int cc = bn + wn * WN + nt * 8 + (lane & 3) * 2;
            *(float2*)&C[(size_t)r0 * ldc + cc] =
                make_float2(acc[mt][nt][0], acc[mt][nt][1]);
            *(float2*)&C[(size_t)(r0 + 8) * ldc + cc] =
                make_float2(acc[mt][nt][2], acc[mt][nt][3]);
        }
    }
}

// ---------------- layernorm + residual + bf16 split ----------------
__global__ void __launch_bounds__(128) ln_kernel(
    const float* __restrict__ x, const float* __restrict__ w,
    const float* __restrict__ bb, float* __restrict__ resid)
{
    int row = blockIdx.x;
    const float* xr = x + (size_t)row * DMODEL;
    int tid = threadIdx.x;
    float v[4];
    float s = 0.f;
#pragma unroll
    for (int i = 0; i < 4; i++) { v[i] = xr[tid + i*128]; s += v[i]; }
#pragma unroll
    for (int o = 16; o; o >>= 1) s += __shfl_xor_sync(0xffffffffu, s, o);
    __shared__ float red[8];
    if ((tid & 31) == 0) red[tid >> 5] = s;
    __syncthreads();
    float mu = (red[0] + red[1] + red[2] + red[3]) * (1.f / DMODEL);
    float q = 0.f;
#pragma unroll
    for (int i = 0; i < 4; i++) { float c = v[i] - mu; q += c * c; }
#pragma unroll
    for (int o = 16; o; o >>= 1) q += __shfl_xor_sync(0xffffffffu, q, o);
    if ((tid & 31) == 0) red[4 + (tid >> 5)] = q;
    __syncthreads();
    float var = (red[4] + red[5] + red[6] + red[7]) * (1.f / DMODEL);
    float rs = rsqrtf(var + 1e-5f);
#pragma unroll
    for (int i = 0; i < 4; i++) {
        int c = tid + i*128;
        float hv = (v[i] - mu) * rs * w[c] + bb[c];
        size_t idx = (size_t)row * DMODEL + c;
        __nv_bfloat16 hh = __float2bfloat16(hv);
        g_hh[idx] = hh;
        g_hl[idx] = __float2bfloat16(hv - __bfloat162float(hh));
        resid[idx] = v[i];
    }
}

// ---------------- fp32 SGEMM (dt_proj): C = A[M,K] @ B[N,K]^T ---------------
// EPI==1: C = softplus(C + bias[n]), coalesced float4 stores.
template<int EPI>
__global__ void __launch_bounds__(256) sgemm_nt(
    int a_id, int lda, const float* __restrict__ Bw, int ldb,
    float* __restrict__ Cext, int c_id, int ldc,
    int Kd, const float* __restrict__ bias)
{
    const float* __restrict__ A = (const float*)g_ptrs[a_id];
    float* __restrict__ C = (c_id >= 0) ? (float*)g_ptrs[c_id] : Cext;
    __shared__ float As[16][132];
    __shared__ float Bs[16][68];
    int tid = threadIdx.x;
    int bm = blockIdx.y * 128, bn = blockIdx.x * 64;
    int tx = tid & 15, ty = tid >> 4;
    int arow = tid >> 1, ak = (tid & 1) * 8;
    int brow = tid >> 2, bk = (tid & 3) * 4;
    const float* Ag = A + (size_t)(bm + arow) * lda + ak;
    const float* Bg = Bw + (size_t)(bn + brow) * ldb + bk;
    float acc[8][4];
#pragma unroll
    for (int i = 0; i < 8; i++)
#pragma unroll
        for (int j = 0; j < 4; j++) acc[i][j] = 0.f;

    for (int k0 = 0; k0 < Kd; k0 += 16) {
        float4 a0 = *(const float4*)(Ag + k0);
        float4 a1 = *(const float4*)(Ag + k0 + 4);
        float4 b0 = *(const float4*)(Bg + k0);
        __syncthreads();
        As[ak+0][arow] = a0.x; As[ak+1][arow] = a0.y;
        As[ak+2][arow] = a0.z; As[ak+3][arow] = a0.w;
        As[ak+4][arow] = a1.x; As[ak+5][arow] = a1.y;
        As[ak+6][arow] = a1.z; As[ak+7][arow] = a1.w;
        Bs[bk+0][brow] = b0.x; Bs[bk+1][brow] = b0.y;
        Bs[bk+2][brow] = b0.z; Bs[bk+3][brow] = b0.w;
        __syncthreads();
#pragma unroll
        for (int k = 0; k < 16; k++) {
            float4 m0 = *(const float4*)&As[k][ty*8];
            float4 m1 = *(const float4*)&As[k][ty*8 + 4];
            float4 n0 = *(const float4*)&Bs[k][tx*4];
            float am[8] = {m0.x, m0.y, m0.z, m0.w, m1.x, m1.y, m1.z, m1.w};
            float bv[4] = {n0.x, n0.y, n0.z, n0.w};
#pragma unroll
            for (int i = 0; i < 8; i++)
#pragma unroll
                for (int j = 0; j < 4; j++)
                    acc[i][j] = fmaf(am[i], bv[j], acc[i][j]);
        }
    }
#pragma unroll
    for (int i = 0; i < 8; i++) {
        float vals[4];
#pragma unroll
        for (int j = 0; j < 4; j++) {
            float v = acc[i][j];
            if (EPI == 1) {
                v += bias[bn + tx*4 + j];
                v = (v > 20.f) ? v : log1pf(expf(v));
            }
            vals[j] = v;
        }
        float4 o; o.x = vals[0]; o.y = vals[1]; o.z = vals[2]; o.w = vals[3];
        *(float4*)&C[(size_t)(bm + ty*8 + i) * ldc + bn + tx*4] = o;
    }
}

// ---------------- causal depthwise conv (K=4) + silu + bf16 split -------------
__global__ void __launch_bounds__(256) conv_silu_kernel(
    const float* __restrict__ cw0, const float* __restrict__ cb0,
    const float* __restrict__ cw1, const float* __restrict__ cb1)
{
    int dir = blockIdx.y;
    unsigned e = blockIdx.x * 256 + threadIdx.x;
    int d = e & (DINNER - 1);
    int m = e >> 10;
    int b = m >> 11, t = m & (LL - 1);
    const float* cw = dir ? cw1 : cw0;
    const float* cb = dir ? cb1 : cb0;
    float acc = cb[d];
#pragma unroll
    for (int k = 0; k < 4; k++) {
        int s = t - 3 + k;
        if (s >= 0) {
            int l = dir ? (LL - 1 - s) : s;
            acc += cw[d*4 + k] * g_xz[(size_t)((b << 11) + l) * (2*DINNER) + d];
        }
    }
    float sv = acc / (1.f + __expf(-acc));
    g_xc[dir][e] = sv;
    __nv_bfloat16 h = __float2bfloat16(sv);
    g_xch[dir][e] = h;
    g_xcl[dir][e] = __float2bfloat16(sv - __bfloat162float(h));
}

// ---------------- selective scan: 16 lanes = 16 states, 2 channels/warp -------
// dt, x as linear loads; {B,C} as ONE float2 (pre-interleaved via weight permute).
__global__ void __launch_bounds__(256) scan_kernel(
    const float* __restrict__ A_log0, const float* __restrict__ Dp0,
    const float* __restrict__ A_log1, const float* __restrict__ Dp1)
{
    int dir = blockIdx.y;
    const float* A_log = dir ? A_log1 : A_log0;
    const float* Dp    = dir ? Dp1    : Dp0;
    int tid = threadIdx.x;
    int w = tid >> 5, lane = tid & 31, half = lane >> 4, n = lane & 15;
    int c = blockIdx.x * 16 + w*2 + half;
    int b = c >> 10, d = c & (DINNER - 1);
    float Acoef = -expf(A_log[d*NSTATE + n]);
    float Dd = Dp[d];
    const float* pdt = &g_dt[dir][(size_t)(b*LL) * DINNER + d];
    const float* px  = &g_xc[dir][(size_t)(b*LL) * DINNER + d];
    const float2* pbc = (const float2*)&g_xdbl[dir][(size_t)(b*LL) * 64 + 32 + 2*n];
    float* py = &g_y[dir][(size_t)(b*LL) * DINNER + d];
    float h = 0.f;
#pragma unroll 4
    for (int t = 0; t < LL; t++) {
        float dtv = __ldg(pdt);
        float xv  = __ldg(px);
        float2 bc = *pbc;          // {B_n, C_n}
        float dA = __expf(dtv * Acoef);
        h = fmaf(dA, h, dtv * bc.x * xv);
        float p = h * bc.y;
        p += __shfl_xor_sync(0xffffffffu, p, 8);
        p += __shfl_xor_sync(0xffffffffu, p, 4);
        p += __shfl_xor_sync(0xffffffffu, p, 2);
        p += __shfl_xor_sync(0xffffffffu, p, 1);
        if (n == 0) *py = p + xv * Dd;
        pdt += DINNER; px += DINNER; pbc += 32; py += DINNER;
    }
}

// ---------------- combine: 0.5 * silu(z) * (y_f + rev(y_r)) -> bf16 split -----
__global__ void __launch_bounds__(256) combine_kernel()
{
    unsigned e = blockIdx.x * 256 + threadIdx.x;
    int d = e & (DINNER - 1);
    int m = e >> 10;
    int b = m >> 11, l = m & (LL - 1);
    float z = g_xz[(size_t)m * (2*DINNER) + DINNER + d];
    float sz = z / (1.f + __expf(-z));
    float yf = g_y[0][e];
    float yr = g_y[1][(size_t)((b << 11) + (LL - 1 - l)) * DINNER + d];
    float v = 0.5f * sz * (yf + yr);
    __nv_bfloat16 h = __float2bfloat16(v);
    g_ach[e] = h;
    g_acl[e] = __float2bfloat16(v - __bfloat162float(h));
}

// ---------------- launch ----------------
extern "C" void kernel_launch(void* const* d_in, const int* in_sizes, int n_in,
                              void* d_out, int out_size)
{
    const float* hs        = (const float*)d_in[0];
    const float* norm_w    = (const float*)d_in[1];
    const float* norm_b    = (const float*)d_in[2];
    const float* in_proj_w = (const float*)d_in[3];
    const float* out_proj_w= (const float*)d_in[4];
    const float* conv_w    = (const float*)d_in[5];
    const float* conv_b    = (const float*)d_in[6];
    const float* x_proj_w  = (const float*)d_in[7];
    const float* dt_proj_w = (const float*)d_in[8];
    const float* dt_proj_b = (const float*)d_in[9];
    const float* A_log     = (const float*)d_in[10];
    const float* Dp        = (const float*)d_in[11];
    const float* conv_w_b  = (const float*)d_in[12];
    const float* conv_b_b  = (const float*)d_in[13];
    const float* x_proj_w_b= (const float*)d_in[14];
    const float* dt_proj_w_b=(const float*)d_in[15];
    const float* dt_proj_b_b=(const float*)d_in[16];
    const float* A_log_b   = (const float*)d_in[17];
    const float* D_b       = (const float*)d_in[18];

    float* out   = (float*)d_out;
    float* resid = out + (size_t)MTOT * DMODEL;

    const int SM128 = 2 * (128*40*2 + 128*40*2);   // 40960 B
    const int SM64  = 2 * (128*40*2 + 64*40*2);    // 30720 B

    // fused g_ptrs init + weight splits (x_proj rows permuted for B/C interleave)
    wsplit_kernel<<<4096 + 512 + 2048, 256>>>(in_proj_w, x_proj_w, x_proj_w_b, out_proj_w);

    // layernorm + residual + h split
    ln_kernel<<<MTOT, 128>>>(hs, norm_w, norm_b, resid);

    // in_proj: g_xz[4096,2048] = h[4096,512] @ in_proj_w[2048,512]^T
    mma_gemm<128><<<dim3(2048/128, MTOT/128, 1), 256, SM128>>>(
        10, 11, 12, 13, 14, nullptr, DMODEL, 2048);

    // conv + silu + bf16 split, both directions (scan order)
    conv_silu_kernel<<<dim3(MTOT*DINNER/256, 2), 256>>>(
        conv_w, conv_b, conv_w_b, conv_b_b);

    // x_proj both dirs: g_xdbl[4096,64] = xc @ x_proj_w_perm[64,1024]^T
    mma_gemm<64><<<dim3(1, MTOT/128, 2), 256, SM64>>>(
        0, 2, 4, 6, 8, nullptr, DINNER, 64);

    // dt per dir: softplus(xdbl[:, :32] @ dt_proj_w[1024,32]^T + bias) -> g_dt
    sgemm_nt<1><<<dim3(1024/64, MTOT/128), 256>>>(
        8, 64, dt_proj_w,   32, nullptr, 20, DINNER, 32, dt_proj_b);
    sgemm_nt<1><<<dim3(1024/64, MTOT/128), 256>>>(
        9, 64, dt_proj_w_b, 32, nullptr, 21, DINNER, 32, dt_proj_b_b);

    // selective scan, both directions
    scan_kernel<<<dim3(BB*DINNER/16, 2), 256>>>(A_log, Dp, A_log_b, D_b);

    // combine + silu(z) gating + split
    combine_kernel<<<(unsigned)((size_t)MTOT*DINNER/256), 256>>>();

    // out_proj: out[4096,512] = ac[4096,1024] @ out_proj_w[512,1024]^T
    mma_gemm<128><<<dim3(512/128, MTOT/128, 1), 256, SM128>>>(
        15, 16, 17, 18, -1, out, DINNER, DMODEL);
}

// round 10
// speedup vs baseline: 2.0555x; 1.7279x over previous
#include <cuda_runtime.h>
#include <cuda_bf16.h>
#include <math.h>
#include <stdint.h>

#define BB 2
#define LL 2048
#define DMODEL 512
#define DINNER 1024
#define NSTATE 16
#define MTOT (BB*LL)          // 4096 rows

// ------------- scratch (static device memory; 256B-aligned) ----------------
__device__ __align__(256) float g_xz[(size_t)MTOT*2*DINNER];      // in_proj out (x | z)
__device__ __align__(256) float g_xc[2][(size_t)MTOT*DINNER];     // conv+silu (scan order)
__device__ __align__(256) float g_dt[2][(size_t)MTOT*DINNER];     // softplus(dt)
__device__ __align__(256) float g_xdbl[2][(size_t)MTOT*64];       // x_proj out (dt 32 | B 16 | C 16)
__device__ __align__(256) float g_y[2][(size_t)MTOT*DINNER];      // scan output

// bf16 split operands (hi/lo)
__device__ __align__(256) __nv_bfloat16 g_hh[(size_t)MTOT*DMODEL];
__device__ __align__(256) __nv_bfloat16 g_hl[(size_t)MTOT*DMODEL];
__device__ __align__(256) __nv_bfloat16 g_wih[2048*512];
__device__ __align__(256) __nv_bfloat16 g_wil[2048*512];
__device__ __align__(256) __nv_bfloat16 g_xch[2][(size_t)MTOT*DINNER];
__device__ __align__(256) __nv_bfloat16 g_xcl[2][(size_t)MTOT*DINNER];
__device__ __align__(256) __nv_bfloat16 g_xwh[2][64*1024];
__device__ __align__(256) __nv_bfloat16 g_xwl[2][64*1024];
__device__ __align__(256) __nv_bfloat16 g_ach[(size_t)MTOT*DINNER];
__device__ __align__(256) __nv_bfloat16 g_acl[(size_t)MTOT*DINNER];
__device__ __align__(256) __nv_bfloat16 g_woh[512*1024];
__device__ __align__(256) __nv_bfloat16 g_wol[512*1024];

__device__ void* g_ptrs[24];

// ---------------- fused: g_ptrs init + all 4 weight splits (NO permute) -------
__global__ void __launch_bounds__(256) wsplit_kernel(
    const float* __restrict__ w_in, const float* __restrict__ w_xf,
    const float* __restrict__ w_xb, const float* __restrict__ w_out)
{
    int bid = blockIdx.x, tid = threadIdx.x;
    if (bid == 0 && tid == 0) {
        g_ptrs[0]  = g_xch[0]; g_ptrs[1]  = g_xch[1];
        g_ptrs[2]  = g_xcl[0]; g_ptrs[3]  = g_xcl[1];
        g_ptrs[4]  = g_xwh[0]; g_ptrs[5]  = g_xwh[1];
        g_ptrs[6]  = g_xwl[0]; g_ptrs[7]  = g_xwl[1];
        g_ptrs[8]  = g_xdbl[0]; g_ptrs[9] = g_xdbl[1];
        g_ptrs[10] = g_hh;  g_ptrs[11] = g_hl;
        g_ptrs[12] = g_wih; g_ptrs[13] = g_wil;
        g_ptrs[14] = g_xz;
        g_ptrs[15] = g_ach; g_ptrs[16] = g_acl;
        g_ptrs[17] = g_woh; g_ptrs[18] = g_wol;
        g_ptrs[20] = g_dt[0]; g_ptrs[21] = g_dt[1];
    }
    if (bid < 4096) {                       // in_proj_w: 1M elems
        int i = bid * 256 + tid;
        float x = w_in[i];
        __nv_bfloat16 h = __float2bfloat16(x);
        g_wih[i] = h;
        g_wil[i] = __float2bfloat16(x - __bfloat162float(h));
    } else if (bid < 4608) {                // x_proj_w fwd/bwd: 2 x 64K
        int z = (bid - 4096) >> 8;          // 0: fwd, 1: bwd
        int i = ((bid - 4096) & 255) * 256 + tid;
        const float* src = z ? w_xb : w_xf;
        float x = src[i];
        __nv_bfloat16 h = __float2bfloat16(x);
        g_xwh[z][i] = h;
        g_xwl[z][i] = __float2bfloat16(x - __bfloat162float(h));
    } else {                                // out_proj_w: 512K
        int i = (bid - 4608) * 256 + tid;
        float x = w_out[i];
        __nv_bfloat16 h = __float2bfloat16(x);
        g_woh[i] = h;
        g_wol[i] = __float2bfloat16(x - __bfloat162float(h));
    }
}

// ====================== baseline-PTX helpers (sm_80-level) ======================
__device__ __forceinline__ uint32_t smem_u32(const void* p) {
    uint32_t a;
    asm("{ .reg .u64 t; cvta.to.shared.u64 t, %1; cvt.u32.u64 %0, t; }" : "=r"(a) : "l"(p));
    return a;
}
#define LDSM4(r, addr) \
    asm volatile("ldmatrix.sync.aligned.m8n8.x4.shared.b16 {%0,%1,%2,%3}, [%4];" \
        : "=r"((r)[0]), "=r"((r)[1]), "=r"((r)[2]), "=r"((r)[3]) : "r"(addr))
#define MMA16816(d, a, b0, b1) \
    asm volatile("mma.sync.aligned.m16n8k16.row.col.f32.bf16.bf16.f32 " \
        "{%0,%1,%2,%3},{%4,%5,%6,%7},{%8,%9},{%0,%1,%2,%3};" \
        : "+f"((d)[0]), "+f"((d)[1]), "+f"((d)[2]), "+f"((d)[3]) \
        : "r"((a)[0]), "r"((a)[1]), "r"((a)[2]), "r"((a)[3]), "r"(b0), "r"(b1))
#define CP_ASYNC16(saddr, gaddr) \
    asm volatile("cp.async.cg.shared.global [%0], [%1], 16;" :: "r"(saddr), "l"(gaddr))
#define CP_COMMIT() asm volatile("cp.async.commit_group;")
#define CP_WAIT(n)  asm volatile("cp.async.wait_group %0;" :: "n"(n))

// ====================== split-bf16 warp-MMA GEMM =============================
// C[M,N] = (Ah+Al)[M,K] @ (Bh+Bl)[N,K]^T via 3 passes (AhBh + AlBh + AhBl).
// BM in {128,64}; BN in {128,64}; BK=32; 256 threads.
// Warp grid: BM=128 -> 4x2 (wm rows x wn cols); BM=64 -> 2x4.
// SMEM rows padded to 40 bf16 (80B) -> conflict-free ldmatrix/cp.async phases.
template<int BM, int BN>
__global__ void __launch_bounds__(256) mma_gemm(
    int ahi, int alo, int bhi, int blo, int c_id,
    float* Cext, int K, int ldc)
{
    extern __shared__ char smem[];
    const int z = blockIdx.z;
    const __nv_bfloat16* Ah = (const __nv_bfloat16*)g_ptrs[ahi + z];
    const __nv_bfloat16* Al = (const __nv_bfloat16*)g_ptrs[alo + z];
    const __nv_bfloat16* Bh = (const __nv_bfloat16*)g_ptrs[bhi + z];
    const __nv_bfloat16* Bl = (const __nv_bfloat16*)g_ptrs[blo + z];
    float* C = (c_id >= 0) ? (float*)g_ptrs[c_id + z] : Cext;

    constexpr int WNW = (BM == 128) ? 2 : 4;   // warps along N
    constexpr int WN  = BN / WNW;              // per-warp n extent
    constexpr int NT8 = WN / 8;
    constexpr int NG  = NT8 / 2;
    constexpr int ASZ = BM * 40 * 2;
    constexpr int BSZ = BN * 40 * 2;
    constexpr int STG = ASZ + BSZ;

    const int tid  = threadIdx.x;
    const int lane = tid & 31, wid = tid >> 5;
    const int wm = wid / WNW, wn = wid % WNW;
    const int bm = blockIdx.y * BM, bn = blockIdx.x * BN;
    uint32_t sb = smem_u32(smem);

    const int KC = K / 32;
    const int NI = 3 * KC;

    const int lrow = (lane & 7) + (wid << 3);   // 8 warps x 8 rows = 64 rows/pass
    const int lchk = (lane >> 3) & 3;           // 4 16B chunks per 64B row

    auto load_stage = [&](int i, int s) {
        int pass = i / KC;
        int k0 = (i - pass * KC) * 32;
        const __nv_bfloat16* sA = (pass == 1) ? Al : Ah;
        const __nv_bfloat16* sB = (pass == 2) ? Bl : Bh;
        uint32_t as = sb + s * STG;
        uint32_t bs = as + ASZ;
#pragma unroll
        for (int h = 0; h < BM / 64; h++) {
            int r = lrow + h * 64;
            CP_ASYNC16(as + (r * 40 + lchk * 8) * 2,
                       sA + (size_t)(bm + r) * K + k0 + lchk * 8);
        }
#pragma unroll
        for (int h = 0; h < BN / 64; h++) {
            int r = lrow + h * 64;
            CP_ASYNC16(bs + (r * 40 + lchk * 8) * 2,
                       sB + (size_t)(bn + r) * K + k0 + lchk * 8);
        }
        CP_COMMIT();
    };

    float acc[2][NT8][4];
#pragma unroll
    for (int mt = 0; mt < 2; mt++)
#pragma unroll
        for (int nt = 0; nt < NT8; nt++)
#pragma unroll
            for (int q = 0; q < 4; q++) acc[mt][nt][q] = 0.f;

    load_stage(0, 0);
    for (int i = 0; i < NI; i++) {
        int s = i & 1;
        if (i + 1 < NI) { load_stage(i + 1, s ^ 1); CP_WAIT(1); }
        else             { CP_WAIT(0); }
        __syncthreads();
        uint32_t as = sb + s * STG, bs = as + ASZ;
#pragma unroll
        for (int kk = 0; kk < 2; kk++) {
            uint32_t a[2][4];
            int kc = kk * 2 + (lane >> 4);
#pragma unroll
            for (int mt = 0; mt < 2; mt++) {
                int r = wm * 32 + mt * 16 + (lane & 15);
                LDSM4(a[mt], as + (r * 40 + kc * 8) * 2);
            }
            uint32_t b[NG][4];
            int bc = kk * 2 + ((lane >> 3) & 1);
            int brl = (lane & 7) + ((lane >> 4) << 3);
#pragma unroll
            for (int g = 0; g < NG; g++) {
                int r = wn * WN + g * 16 + brl;
                LDSM4(b[g], bs + (r * 40 + bc * 8) * 2);
            }
#pragma unroll
            for (int mt = 0; mt < 2; mt++)
#pragma unroll
                for (int nt = 0; nt < NT8; nt++)
                    MMA16816(acc[mt][nt], a[mt],
                             b[nt >> 1][(nt & 1) * 2], b[nt >> 1][(nt & 1) * 2 + 1]);
        }
        __syncthreads();
    }

#pragma unroll
    for (int mt = 0; mt < 2; mt++) {
        int r0 = bm + wm * 32 + mt * 16 + (lane >> 2);
#pragma unroll
        for (int nt = 0; nt < NT8; nt++) {
            int cc = bn + wn * WN + nt * 8 + (lane & 3) * 2;
            *(float2*)&C[(size_t)r0 * ldc + cc] =
                make_float2(acc[mt][nt][0], acc[mt][nt][1]);
            *(float2*)&C[(size_t)(r0 + 8) * ldc + cc] =
                make_float2(acc[mt][nt][2], acc[mt][nt][3]);
        }
    }
}

// ---------------- layernorm + residual + bf16 split ----------------
__global__ void __launch_bounds__(128) ln_kernel(
    const float* __restrict__ x, const float* __restrict__ w,
    const float* __restrict__ bb, float* __restrict__ resid)
{
    int row = blockIdx.x;
    const float* xr = x + (size_t)row * DMODEL;
    int tid = threadIdx.x;
    float v[4];
    float s = 0.f;
#pragma unroll
    for (int i = 0; i < 4; i++) { v[i] = xr[tid + i*128]; s += v[i]; }
#pragma unroll
    for (int o = 16; o; o >>= 1) s += __shfl_xor_sync(0xffffffffu, s, o);
    __shared__ float red[8];
    if ((tid & 31) == 0) red[tid >> 5] = s;
    __syncthreads();
    float mu = (red[0] + red[1] + red[2] + red[3]) * (1.f / DMODEL);
    float q = 0.f;
#pragma unroll
    for (int i = 0; i < 4; i++) { float c = v[i] - mu; q += c * c; }
#pragma unroll
    for (int o = 16; o; o >>= 1) q += __shfl_xor_sync(0xffffffffu, q, o);
    if ((tid & 31) == 0) red[4 + (tid >> 5)] = q;
    __syncthreads();
    float var = (red[4] + red[5] + red[6] + red[7]) * (1.f / DMODEL);
    float rs = rsqrtf(var + 1e-5f);
#pragma unroll
    for (int i = 0; i < 4; i++) {
        int c = tid + i*128;
        float hv = (v[i] - mu) * rs * w[c] + bb[c];
        size_t idx = (size_t)row * DMODEL + c;
        __nv_bfloat16 hh = __float2bfloat16(hv);
        g_hh[idx] = hh;
        g_hl[idx] = __float2bfloat16(hv - __bfloat162float(hh));
        resid[idx] = v[i];
    }
}

// ---------------- fp32 SGEMM (dt_proj, both dirs via z): ---------------------
// C = softplus(A[M,32] @ B[1024,32]^T + bias), coalesced float4 stores.
__global__ void __launch_bounds__(256) sgemm_dt(
    const float* __restrict__ Bw0, const float* __restrict__ Bw1,
    const float* __restrict__ bias0, const float* __restrict__ bias1)
{
    const int zz = blockIdx.z;
    const float* __restrict__ A = (const float*)g_ptrs[8 + zz];
    float* __restrict__ C = (float*)g_ptrs[20 + zz];
    const float* __restrict__ Bw = zz ? Bw1 : Bw0;
    const float* __restrict__ bias = zz ? bias1 : bias0;
    const int lda = 64, ldb = 32, ldc = DINNER, Kd = 32;
    __shared__ float As[16][132];
    __shared__ float Bs[16][68];
    int tid = threadIdx.x;
    int bm = blockIdx.y * 128, bn = blockIdx.x * 64;
    int tx = tid & 15, ty = tid >> 4;
    int arow = tid >> 1, ak = (tid & 1) * 8;
    int brow = tid >> 2, bk = (tid & 3) * 4;
    const float* Ag = A + (size_t)(bm + arow) * lda + ak;
    const float* Bg = Bw + (size_t)(bn + brow) * ldb + bk;
    float acc[8][4];
#pragma unroll
    for (int i = 0; i < 8; i++)
#pragma unroll
        for (int j = 0; j < 4; j++) acc[i][j] = 0.f;

    for (int k0 = 0; k0 < Kd; k0 += 16) {
        float4 a0 = *(const float4*)(Ag + k0);
        float4 a1 = *(const float4*)(Ag + k0 + 4);
        float4 b0 = *(const float4*)(Bg + k0);
        __syncthreads();
        As[ak+0][arow] = a0.x; As[ak+1][arow] = a0.y;
        As[ak+2][arow] = a0.z; As[ak+3][arow] = a0.w;
        As[ak+4][arow] = a1.x; As[ak+5][arow] = a1.y;
        As[ak+6][arow] = a1.z; As[ak+7][arow] = a1.w;
        Bs[bk+0][brow] = b0.x; Bs[bk+1][brow] = b0.y;
        Bs[bk+2][brow] = b0.z; Bs[bk+3][brow] = b0.w;
        __syncthreads();
#pragma unroll
        for (int k = 0; k < 16; k++) {
            float4 m0 = *(const float4*)&As[k][ty*8];
            float4 m1 = *(const float4*)&As[k][ty*8 + 4];
            float4 n0 = *(const float4*)&Bs[k][tx*4];
            float am[8] = {m0.x, m0.y, m0.z, m0.w, m1.x, m1.y, m1.z, m1.w};
            float bv[4] = {n0.x, n0.y, n0.z, n0.w};
#pragma unroll
            for (int i = 0; i < 8; i++)
#pragma unroll
                for (int j = 0; j < 4; j++)
                    acc[i][j] = fmaf(am[i], bv[j], acc[i][j]);
        }
    }
#pragma unroll
    for (int i = 0; i < 8; i++) {
        float vals[4];
#pragma unroll
        for (int j = 0; j < 4; j++) {
            float v = acc[i][j] + bias[bn + tx*4 + j];
            vals[j] = (v > 20.f) ? v : log1pf(expf(v));
        }
        float4 o; o.x = vals[0]; o.y = vals[1]; o.z = vals[2]; o.w = vals[3];
        *(float4*)&C[(size_t)(bm + ty*8 + i) * ldc + bn + tx*4] = o;
    }
}

// ---------------- causal depthwise conv (K=4) + silu + bf16 split -------------
__global__ void __launch_bounds__(256) conv_silu_kernel(
    const float* __restrict__ cw0, const float* __restrict__ cb0,
    const float* __restrict__ cw1, const float* __restrict__ cb1)
{
    int dir = blockIdx.y;
    unsigned e = blockIdx.x * 256 + threadIdx.x;
    int d = e & (DINNER - 1);
    int m = e >> 10;
    int b = m >> 11, t = m & (LL - 1);
    const float* cw = dir ? cw1 : cw0;
    const float* cb = dir ? cb1 : cb0;
    float acc = cb[d];
#pragma unroll
    for (int k = 0; k < 4; k++) {
        int s = t - 3 + k;
        if (s >= 0) {
            int l = dir ? (LL - 1 - s) : s;
            acc += cw[d*4 + k] * g_xz[(size_t)((b << 11) + l) * (2*DINNER) + d];
        }
    }
    float sv = acc / (1.f + __expf(-acc));
    g_xc[dir][e] = sv;
    __nv_bfloat16 h = __float2bfloat16(sv);
    g_xch[dir][e] = h;
    g_xcl[dir][e] = __float2bfloat16(sv - __bfloat162float(h));
}

// ---------------- selective scan: 16 lanes = 16 states, 2 channels/warp -------
__global__ void __launch_bounds__(256) scan_kernel(
    const float* __restrict__ A_log0, const float* __restrict__ Dp0,
    const float* __restrict__ A_log1, const float* __restrict__ Dp1)
{
    int dir = blockIdx.y;
    const float* A_log = dir ? A_log1 : A_log0;
    const float* Dp    = dir ? Dp1    : Dp0;
    int tid = threadIdx.x;
    int w = tid >> 5, lane = tid & 31, half = lane >> 4, n = lane & 15;
    int c = blockIdx.x * 16 + w*2 + half;
    int b = c >> 10, d = c & (DINNER - 1);
    float Acoef = -expf(A_log[d*NSTATE + n]);
    float Dd = Dp[d];
    const float* pdt = &g_dt[dir][(size_t)(b*LL) * DINNER + d];
    const float* px  = &g_xc[dir][(size_t)(b*LL) * DINNER + d];
    const float* pb  = &g_xdbl[dir][(size_t)(b*LL) * 64 + 32 + n];
    float* py        = &g_y[dir][(size_t)(b*LL) * DINNER + d];
    float h = 0.f;
#pragma unroll 4
    for (int t = 0; t < LL; t++) {
        float dtv = __ldg(pdt);
        float xv  = __ldg(px);
        float Bn  = __ldg(pb);
        float Cn  = __ldg(pb + 16);
        float dA  = __expf(dtv * Acoef);
        h = fmaf(dA, h, dtv * Bn * xv);
        float p = h * Cn;
        p += __shfl_xor_sync(0xffffffffu, p, 8);
        p += __shfl_xor_sync(0xffffffffu, p, 4);
        p += __shfl_xor_sync(0xffffffffu, p, 2);
        p += __shfl_xor_sync(0xffffffffu, p, 1);
        if (n == 0) *py = p + xv * Dd;
        pdt += DINNER; px += DINNER; pb += 64; py += DINNER;
    }
}

// ---------------- combine: 0.5 * silu(z) * (y_f + rev(y_r)) -> bf16 split -----
__global__ void __launch_bounds__(256) combine_kernel()
{
    unsigned e = blockIdx.x * 256 + threadIdx.x;
    int d = e & (DINNER - 1);
    int m = e >> 10;
    int b = m >> 11, l = m & (LL - 1);
    float z = g_xz[(size_t)m * (2*DINNER) + DINNER + d];
    float sz = z / (1.f + __expf(-z));
    float yf = g_y[0][e];
    float yr = g_y[1][(size_t)((b << 11) + (LL - 1 - l)) * DINNER + d];
    float v = 0.5f * sz * (yf + yr);
    __nv_bfloat16 h = __float2bfloat16(v);
    g_ach[e] = h;
    g_acl[e] = __float2bfloat16(v - __bfloat162float(h));
}

// ---------------- launch ----------------
extern "C" void kernel_launch(void* const* d_in, const int* in_sizes, int n_in,
                              void* d_out, int out_size)
{
    const float* hs        = (const float*)d_in[0];
    const float* norm_w    = (const float*)d_in[1];
    const float* norm_b    = (const float*)d_in[2];
    const float* in_proj_w = (const float*)d_in[3];
    const float* out_proj_w= (const float*)d_in[4];
    const float* conv_w    = (const float*)d_in[5];
    const float* conv_b    = (const float*)d_in[6];
    const float* x_proj_w  = (const float*)d_in[7];
    const float* dt_proj_w = (const float*)d_in[8];
    const float* dt_proj_b = (const float*)d_in[9];
    const float* A_log     = (const float*)d_in[10];
    const float* Dp        = (const float*)d_in[11];
    const float* conv_w_b  = (const float*)d_in[12];
    const float* conv_b_b  = (const float*)d_in[13];
    const float* x_proj_w_b= (const float*)d_in[14];
    const float* dt_proj_w_b=(const float*)d_in[15];
    const float* dt_proj_b_b=(const float*)d_in[16];
    const float* A_log_b   = (const float*)d_in[17];
    const float* D_b       = (const float*)d_in[18];

    float* out   = (float*)d_out;
    float* resid = out + (size_t)MTOT * DMODEL;

    const int SM128 = 2 * (128*40*2 + 128*40*2);   // 40960 B
    const int SM64  = 2 * (64*40*2 + 64*40*2);     // 20480 B

    // fused g_ptrs init + weight splits
    wsplit_kernel<<<4096 + 512 + 2048, 256>>>(in_proj_w, x_proj_w, x_proj_w_b, out_proj_w);

    // layernorm + residual + h split
    ln_kernel<<<MTOT, 128>>>(hs, norm_w, norm_b, resid);

    // in_proj: g_xz[4096,2048] = h[4096,512] @ in_proj_w[2048,512]^T
    mma_gemm<128,128><<<dim3(2048/128, MTOT/128, 1), 256, SM128>>>(
        10, 11, 12, 13, 14, nullptr, DMODEL, 2048);

    // conv + silu + bf16 split, both directions (scan order)
    conv_silu_kernel<<<dim3(MTOT*DINNER/256, 2), 256>>>(
        conv_w, conv_b, conv_w_b, conv_b_b);

    // x_proj both dirs: g_xdbl[4096,64] = xc @ x_proj_w[64,1024]^T  (BM=64 -> 128 blocks)
    mma_gemm<64,64><<<dim3(1, MTOT/64, 2), 256, SM64>>>(
        0, 2, 4, 6, 8, nullptr, DINNER, 64);

    // dt both dirs: softplus(xdbl[:, :32] @ dt_proj_w[1024,32]^T + bias) -> g_dt
    sgemm_dt<<<dim3(1024/64, MTOT/128, 2), 256>>>(
        dt_proj_w, dt_proj_w_b, dt_proj_b, dt_proj_b_b);

    // selective scan, both directions
    scan_kernel<<<dim3(BB*DINNER/16, 2), 256>>>(A_log, Dp, A_log_b, D_b);

    // combine + silu(z) gating + split
    combine_kernel<<<(unsigned)((size_t)MTOT*DINNER/256), 256>>>();

    // out_proj: out[4096,512] = ac[4096,1024] @ out_proj_w[512,1024]^T
    mma_gemm<128,128><<<dim3(512/128, MTOT/128, 1), 256, SM128>>>(
        15, 16, 17, 18, -1, out, DINNER, DMODEL);
}